// round 11
// baseline (speedup 1.0000x reference)
#include <cuda_runtime.h>
#include <cstdint>

// YOLO loss: pred/target (bs, 7, 7, 30) f32 -> scalar f32.
// R10 pipeline (grid-strided cp.async.bulk 3-stage ring, TILE=128,
// single-thread issue, mbarrier completion, one __syncthreads per tile,
// last-block finalize) + cp.async.bulk.prefetch.L2: a dependency-free
// prefetch stream runs 6 tiles ahead of the ring so DRAM demand is
// decoupled from consumer/stage-recycle timing; bulk copies then hit L2.

#define S_GRID 7
#define CH 30
#define TILE 128
#define NTHREADS 128
#define STAGES 3
#define PF_DIST 6                           // prefetch look-ahead (tiles)
#define SFLOATS (TILE * CH)                 // 3840 floats per tensor per stage
#define STAGE_FLOATS (2 * SFLOATS)          // 7680 floats (pred + targ)
#define STAGE_BYTES (STAGE_FLOATS * 4)      // 30720 B
#define HALF_BYTES (SFLOATS * 4)            // 15360 B
#define SMEM_BYTES (STAGES * STAGE_BYTES)   // 92160 B -> 2 CTAs/SM
#define MAX_BLOCKS 296                      // 2 * 148

__device__ double g_acc = 0.0;
__device__ unsigned int g_counter = 0u;

__device__ __forceinline__ void mbar_init(uint32_t mbar, uint32_t cnt) {
    asm volatile("mbarrier.init.shared.b64 [%0], %1;" :: "r"(mbar), "r"(cnt) : "memory");
}
__device__ __forceinline__ void mbar_expect_tx(uint32_t mbar, uint32_t bytes) {
    asm volatile("mbarrier.arrive.expect_tx.shared.b64 _, [%0], %1;"
                 :: "r"(mbar), "r"(bytes) : "memory");
}
__device__ __forceinline__ void mbar_wait(uint32_t mbar, uint32_t parity) {
    asm volatile(
        "{\n\t"
        ".reg .pred P;\n\t"
        "WAIT_%=:\n\t"
        "mbarrier.try_wait.parity.acquire.cta.shared::cta.b64 P, [%0], %1, 0x989680;\n\t"
        "@P bra.uni DONE_%=;\n\t"
        "bra.uni WAIT_%=;\n\t"
        "DONE_%=:\n\t"
        "}" :: "r"(mbar), "r"(parity) : "memory");
}
__device__ __forceinline__ void bulk_g2s(uint32_t dst, const void* src,
                                         uint32_t bytes, uint32_t mbar) {
    asm volatile(
        "cp.async.bulk.shared::cta.global.mbarrier::complete_tx::bytes [%0], [%1], %2, [%3];"
        :: "r"(dst), "l"(src), "r"(bytes), "r"(mbar) : "memory");
}
__device__ __forceinline__ void bulk_prefetch_l2(const void* src, uint32_t bytes) {
    asm volatile("cp.async.bulk.prefetch.L2.global [%0], %1;"
                 :: "l"(src), "r"(bytes));
}

// Issue one tile (pred+targ halves) into a stage; called by tid 0 only.
__device__ __forceinline__ void issue_tile_bulk(uint32_t smem_u32, int stage,
                                                uint32_t mbar,
                                                const char* __restrict__ pred,
                                                const char* __restrict__ targ,
                                                long long tile) {
    const uint32_t dst = smem_u32 + (uint32_t)stage * STAGE_BYTES;
    mbar_expect_tx(mbar, STAGE_BYTES);
    bulk_g2s(dst,              pred + tile * (long long)HALF_BYTES, HALF_BYTES, mbar);
    bulk_g2s(dst + HALF_BYTES, targ + tile * (long long)HALF_BYTES, HALF_BYTES, mbar);
}

__device__ __forceinline__ void prefetch_tile(const char* __restrict__ pred,
                                              const char* __restrict__ targ,
                                              long long tile) {
    bulk_prefetch_l2(pred + tile * (long long)HALF_BYTES, HALF_BYTES);
    bulk_prefetch_l2(targ + tile * (long long)HALF_BYTES, HALF_BYTES);
}

// Per-cell loss; p/t point at 30 contiguous floats (smem or gmem).
__device__ __forceinline__ float cell_loss(const float* __restrict__ p,
                                           const float* __restrict__ t)
{
    const float obj = (t[4] > 0.0f) ? 1.0f : 0.0f;

    const float dn0 = p[4] - t[4];
    const float dn1 = p[9] - t[9];
    const float noobj = dn0 * dn0 + dn1 * dn1;

    float cls = 0.0f;
    #pragma unroll
    for (int k = 10; k < 30; k++) {
        const float d = p[k] - t[k];
        cls = fmaf(d, d, cls);
    }

    const float invS = 1.0f / (float)S_GRID;
    const float tx = t[0] * invS, ty = t[1] * invS;
    const float tw = t[2], th = t[3];
    const float tx0 = tx - 0.5f * tw, tx1 = tx + 0.5f * tw;
    const float ty0 = ty - 0.5f * th, ty1 = ty + 0.5f * th;
    const float area_t = tw * th;

    float iou0 = 0.0f, iou1 = 0.0f;
    #pragma unroll
    for (int b = 0; b < 2; b++) {
        const float* q = p + 5 * b;
        const float px = q[0] * invS, py = q[1] * invS;
        const float pw = q[2], ph = q[3];
        const float lx = fmaxf(px - 0.5f * pw, tx0);
        const float rx = fminf(px + 0.5f * pw, tx1);
        const float ly = fmaxf(py - 0.5f * ph, ty0);
        const float ry = fminf(py + 0.5f * ph, ty1);
        const float wx = fmaxf(rx - lx, 0.0f);
        const float wy = fmaxf(ry - ly, 0.0f);
        const float inter = wx * wy;
        const float uni = fmaxf(pw * ph + area_t - inter, 1e-10f);
        const float iou = inter / uni;
        if (b == 0) iou0 = iou; else iou1 = iou;
    }
    // jnp.argmax picks first max -> box 1 only on strict greater.
    const int rb = (iou1 > iou0) ? 1 : 0;
    const float miou = fmaxf(iou0, iou1);

    const float* q  = p + 5 * rb;
    const float* tq = t + 5 * rb;
    const float dx = q[0] - tq[0];
    const float dy = q[1] - tq[1];
    const float lxy = dx * dx + dy * dy;
    const float dw = sqrtf(q[2]) - sqrtf(tq[2]);
    const float dh = sqrtf(q[3]) - sqrtf(tq[3]);
    const float lwh = dw * dw + dh * dh;
    const float dob = q[4] - miou;
    const float lobj = dob * dob;

    return obj * (5.0f * (lxy + lwh) + lobj + cls)
         + 0.5f * (1.0f - obj) * noobj;
}

__global__ __launch_bounds__(NTHREADS) void yolo_loss_kernel(
    const float* __restrict__ pred,
    const float* __restrict__ targ,
    int total_cells,
    float* __restrict__ out,
    double inv_bs)
{
    extern __shared__ float smem[];
    __shared__ __align__(8) uint64_t mbar_storage[STAGES];
    __shared__ float warp_sums[NTHREADS / 32];

    const int tid = threadIdx.x;
    const uint32_t smem_u32 = (uint32_t)__cvta_generic_to_shared(smem);
    const uint32_t mbar0 = (uint32_t)__cvta_generic_to_shared(mbar_storage);
    const char* predc = (const char*)pred;
    const char* targc = (const char*)targ;

    const int ntiles = total_cells / TILE;
    const int rem = total_cells - ntiles * TILE;
    const long long stride = gridDim.x;

    if (tid == 0) {
        #pragma unroll
        for (int s = 0; s < STAGES; s++) mbar_init(mbar0 + 8u * s, 1u);
    }
    __syncthreads();

    // Prologue: prefetch tiles t0+2g..t0+5g, issue copies for t0, t0+g.
    const long long t0 = blockIdx.x;
    if (tid == 0) {
        #pragma unroll
        for (int j = STAGES - 1; j < PF_DIST; j++) {
            const long long tj = t0 + j * stride;
            if (tj < ntiles) prefetch_tile(predc, targc, tj);
        }
        #pragma unroll
        for (int j = 0; j < STAGES - 1; j++) {
            const long long tj = t0 + j * stride;
            if (tj < ntiles)
                issue_tile_bulk(smem_u32, j, mbar0 + 8u * j, predc, targc, tj);
        }
    }

    float loss = 0.0f;
    unsigned int ph = 0;   // per-stage parity bitmask
    int s = 0;             // stage = k % STAGES
    for (long long t = t0; t < ntiles; t += stride) {
        if (tid == 0) {
            // Dependency-free L2 prefetch, PF_DIST tiles ahead.
            const long long tp = t + PF_DIST * stride;
            if (tp < ntiles) prefetch_tile(predc, targc, tp);

            // Bulk copy into the stage consumed at iteration k-1.
            const long long tn = t + (STAGES - 1) * stride;
            if (tn < ntiles) {
                int sn = s + (STAGES - 1); if (sn >= STAGES) sn -= STAGES;
                issue_tile_bulk(smem_u32, sn, mbar0 + 8u * sn, predc, targc, tn);
            }
        }

        // Wait for this stage's tile.
        mbar_wait(mbar0 + 8u * s, (ph >> s) & 1u);
        ph ^= 1u << s;

        {
            const float* p  = smem + s * STAGE_FLOATS + tid * CH;
            const float* tt = smem + s * STAGE_FLOATS + SFLOATS + tid * CH;
            loss += cell_loss(p, tt);
        }

        __syncthreads();   // single barrier per tile: frees stage for reuse
        if (++s == STAGES) s = 0;
    }

    // Tail cells (total_cells % TILE; zero at bench shape), block 0 from gmem.
    if (rem && blockIdx.x == 0 && tid < rem) {
        const long long c = (long long)ntiles * TILE + tid;
        loss += cell_loss(pred + c * CH, targ + c * CH);
    }

    // Block reduction
    #pragma unroll
    for (int o = 16; o > 0; o >>= 1)
        loss += __shfl_xor_sync(0xffffffffu, loss, o);
    if ((tid & 31) == 0) warp_sums[tid >> 5] = loss;
    __syncthreads();

    if (tid == 0) {
        const float bsum = warp_sums[0] + warp_sums[1] + warp_sums[2] + warp_sums[3];
        atomicAdd(&g_acc, (double)bsum);
        __threadfence();
        const unsigned int ticket = atomicAdd(&g_counter, 1u);
        if (ticket == gridDim.x - 1u) {
            const double total = atomicAdd(&g_acc, 0.0);
            out[0] = (float)(total * inv_bs);
            g_acc = 0.0;          // reset for next graph replay
            __threadfence();
            g_counter = 0u;
        }
    }
}

extern "C" void kernel_launch(void* const* d_in, const int* in_sizes, int n_in,
                              void* d_out, int out_size) {
    const float* pred = (const float*)d_in[0];
    const float* targ = (const float*)d_in[1];
    const long long n = (long long)in_sizes[0];
    const int total_cells = (int)(n / CH);            // bs * 49
    const int bs = total_cells / (S_GRID * S_GRID);
    const int ntiles = total_cells / TILE;

    int grid = ntiles < MAX_BLOCKS ? ntiles : MAX_BLOCKS;
    if (grid < 1) grid = 1;

    cudaFuncSetAttribute(yolo_loss_kernel,
                         cudaFuncAttributeMaxDynamicSharedMemorySize, SMEM_BYTES);
    yolo_loss_kernel<<<grid, NTHREADS, SMEM_BYTES>>>(pred, targ, total_cells,
                                                     (float*)d_out,
                                                     1.0 / (double)bs);
}

// round 12
// speedup vs baseline: 1.0700x; 1.0700x over previous
#include <cuda_runtime.h>
#include <cstdint>

// YOLO loss: pred/target (bs, 7, 7, 30) f32 -> scalar f32.
// R10 pipeline (grid-strided cp.async.bulk 3-stage ring, TILE=128,
// single-thread issue, mbarrier full-completion, last-block finalize),
// with the per-tile __syncthreads replaced by full/empty mbarriers:
// consumers arrive per-warp on an "empty" barrier, producer waits it before
// refilling, so warps may skew up to the ring depth and absorb stalls.

#define S_GRID 7
#define CH 30
#define TILE 128
#define NTHREADS 128
#define STAGES 3
#define SFLOATS (TILE * CH)                 // 3840 floats per tensor per stage
#define STAGE_FLOATS (2 * SFLOATS)          // 7680 floats (pred + targ)
#define STAGE_BYTES (STAGE_FLOATS * 4)      // 30720 B
#define HALF_BYTES (SFLOATS * 4)            // 15360 B
#define SMEM_BYTES (STAGES * STAGE_BYTES)   // 92160 B -> 2 CTAs/SM
#define MAX_BLOCKS 296                      // 2 * 148

__device__ double g_acc = 0.0;
__device__ unsigned int g_counter = 0u;

__device__ __forceinline__ void mbar_init(uint32_t mbar, uint32_t cnt) {
    asm volatile("mbarrier.init.shared.b64 [%0], %1;" :: "r"(mbar), "r"(cnt) : "memory");
}
__device__ __forceinline__ void mbar_expect_tx(uint32_t mbar, uint32_t bytes) {
    asm volatile("mbarrier.arrive.expect_tx.shared.b64 _, [%0], %1;"
                 :: "r"(mbar), "r"(bytes) : "memory");
}
__device__ __forceinline__ void mbar_arrive(uint32_t mbar) {
    asm volatile("mbarrier.arrive.shared.b64 _, [%0];" :: "r"(mbar) : "memory");
}
__device__ __forceinline__ void mbar_wait(uint32_t mbar, uint32_t parity) {
    asm volatile(
        "{\n\t"
        ".reg .pred P;\n\t"
        "WAIT_%=:\n\t"
        "mbarrier.try_wait.parity.acquire.cta.shared::cta.b64 P, [%0], %1, 0x989680;\n\t"
        "@P bra.uni DONE_%=;\n\t"
        "bra.uni WAIT_%=;\n\t"
        "DONE_%=:\n\t"
        "}" :: "r"(mbar), "r"(parity) : "memory");
}
__device__ __forceinline__ void bulk_g2s(uint32_t dst, const void* src,
                                         uint32_t bytes, uint32_t mbar) {
    asm volatile(
        "cp.async.bulk.shared::cta.global.mbarrier::complete_tx::bytes [%0], [%1], %2, [%3];"
        :: "r"(dst), "l"(src), "r"(bytes), "r"(mbar) : "memory");
}

// Issue one tile (pred+targ halves) into a stage; called by tid 0 only.
__device__ __forceinline__ void issue_tile_bulk(uint32_t smem_u32, int stage,
                                                uint32_t mbar,
                                                const char* __restrict__ pred,
                                                const char* __restrict__ targ,
                                                long long tile) {
    const uint32_t dst = smem_u32 + (uint32_t)stage * STAGE_BYTES;
    mbar_expect_tx(mbar, STAGE_BYTES);
    bulk_g2s(dst,              pred + tile * (long long)HALF_BYTES, HALF_BYTES, mbar);
    bulk_g2s(dst + HALF_BYTES, targ + tile * (long long)HALF_BYTES, HALF_BYTES, mbar);
}

// Per-cell loss; p/t point at 30 contiguous floats (smem or gmem).
__device__ __forceinline__ float cell_loss(const float* __restrict__ p,
                                           const float* __restrict__ t)
{
    const float obj = (t[4] > 0.0f) ? 1.0f : 0.0f;

    const float dn0 = p[4] - t[4];
    const float dn1 = p[9] - t[9];
    const float noobj = dn0 * dn0 + dn1 * dn1;

    float cls = 0.0f;
    #pragma unroll
    for (int k = 10; k < 30; k++) {
        const float d = p[k] - t[k];
        cls = fmaf(d, d, cls);
    }

    const float invS = 1.0f / (float)S_GRID;
    const float tx = t[0] * invS, ty = t[1] * invS;
    const float tw = t[2], th = t[3];
    const float tx0 = tx - 0.5f * tw, tx1 = tx + 0.5f * tw;
    const float ty0 = ty - 0.5f * th, ty1 = ty + 0.5f * th;
    const float area_t = tw * th;

    float iou0 = 0.0f, iou1 = 0.0f;
    #pragma unroll
    for (int b = 0; b < 2; b++) {
        const float* q = p + 5 * b;
        const float px = q[0] * invS, py = q[1] * invS;
        const float pw = q[2], ph = q[3];
        const float lx = fmaxf(px - 0.5f * pw, tx0);
        const float rx = fminf(px + 0.5f * pw, tx1);
        const float ly = fmaxf(py - 0.5f * ph, ty0);
        const float ry = fminf(py + 0.5f * ph, ty1);
        const float wx = fmaxf(rx - lx, 0.0f);
        const float wy = fmaxf(ry - ly, 0.0f);
        const float inter = wx * wy;
        const float uni = fmaxf(pw * ph + area_t - inter, 1e-10f);
        const float iou = inter / uni;
        if (b == 0) iou0 = iou; else iou1 = iou;
    }
    // jnp.argmax picks first max -> box 1 only on strict greater.
    const int rb = (iou1 > iou0) ? 1 : 0;
    const float miou = fmaxf(iou0, iou1);

    const float* q  = p + 5 * rb;
    const float* tq = t + 5 * rb;
    const float dx = q[0] - tq[0];
    const float dy = q[1] - tq[1];
    const float lxy = dx * dx + dy * dy;
    const float dw = sqrtf(q[2]) - sqrtf(tq[2]);
    const float dh = sqrtf(q[3]) - sqrtf(tq[3]);
    const float lwh = dw * dw + dh * dh;
    const float dob = q[4] - miou;
    const float lobj = dob * dob;

    return obj * (5.0f * (lxy + lwh) + lobj + cls)
         + 0.5f * (1.0f - obj) * noobj;
}

__global__ __launch_bounds__(NTHREADS) void yolo_loss_kernel(
    const float* __restrict__ pred,
    const float* __restrict__ targ,
    int total_cells,
    float* __restrict__ out,
    double inv_bs)
{
    extern __shared__ float smem[];
    __shared__ __align__(8) uint64_t full_mbar[STAGES];
    __shared__ __align__(8) uint64_t empty_mbar[STAGES];
    __shared__ float warp_sums[NTHREADS / 32];

    const int tid = threadIdx.x;
    const int lane = tid & 31;
    const uint32_t smem_u32 = (uint32_t)__cvta_generic_to_shared(smem);
    const uint32_t full0  = (uint32_t)__cvta_generic_to_shared(full_mbar);
    const uint32_t empty0 = (uint32_t)__cvta_generic_to_shared(empty_mbar);
    const char* predc = (const char*)pred;
    const char* targc = (const char*)targ;

    const int ntiles = total_cells / TILE;
    const int rem = total_cells - ntiles * TILE;
    const long long stride = gridDim.x;

    if (tid == 0) {
        #pragma unroll
        for (int s = 0; s < STAGES; s++) {
            mbar_init(full0  + 8u * s, 1u);           // tx-completion
            mbar_init(empty0 + 8u * s, NTHREADS / 32); // one arrive per warp
        }
    }
    __syncthreads();

    // Prologue: issue tiles t0, t0+g into stages 0,1 (first fills: no wait).
    const long long t0 = blockIdx.x;
    if (tid == 0) {
        #pragma unroll
        for (int j = 0; j < STAGES - 1; j++) {
            const long long tj = t0 + j * stride;
            if (tj < ntiles)
                issue_tile_bulk(smem_u32, j, full0 + 8u * j, predc, targc, tj);
        }
    }

    float loss = 0.0f;
    unsigned int phf = 0;   // full-barrier parity bitmask (consumer side)
    unsigned int phe = 0;   // empty-barrier parity bitmask (producer side)
    int s = 0;              // stage = k % STAGES
    long long k = 0;
    for (long long t = t0; t < ntiles; t += stride, k++) {
        // Producer: refill the stage consumed at iteration k-1 with tile
        // t+2g. First fill of stage (k==0 -> stage 2) skips the empty wait.
        if (tid == 0) {
            const long long tn = t + (STAGES - 1) * stride;
            if (tn < ntiles) {
                int sn = s + (STAGES - 1); if (sn >= STAGES) sn -= STAGES;
                if (k > 0) {
                    mbar_wait(empty0 + 8u * sn, (phe >> sn) & 1u);
                    phe ^= 1u << sn;
                }
                issue_tile_bulk(smem_u32, sn, full0 + 8u * sn, predc, targc, tn);
            }
        }

        // Consumer: wait for this stage's tile.
        mbar_wait(full0 + 8u * s, (phf >> s) & 1u);
        phf ^= 1u << s;

        {
            const float* p  = smem + s * STAGE_FLOATS + tid * CH;
            const float* tt = smem + s * STAGE_FLOATS + SFLOATS + tid * CH;
            loss += cell_loss(p, tt);
        }

        // Per-warp done-reading arrival (release); producer's acquire wait
        // orders the next TMA overwrite after all four warps' reads.
        __syncwarp();
        if (lane == 0) mbar_arrive(empty0 + 8u * s);

        if (++s == STAGES) s = 0;
    }

    // Tail cells (total_cells % TILE; zero at bench shape), block 0 from gmem.
    if (rem && blockIdx.x == 0 && tid < rem) {
        const long long c = (long long)ntiles * TILE + tid;
        loss += cell_loss(pred + c * CH, targ + c * CH);
    }

    // Block reduction (realigns skewed warps).
    #pragma unroll
    for (int o = 16; o > 0; o >>= 1)
        loss += __shfl_xor_sync(0xffffffffu, loss, o);
    if (lane == 0) warp_sums[tid >> 5] = loss;
    __syncthreads();

    if (tid == 0) {
        const float bsum = warp_sums[0] + warp_sums[1] + warp_sums[2] + warp_sums[3];
        atomicAdd(&g_acc, (double)bsum);
        __threadfence();
        const unsigned int ticket = atomicAdd(&g_counter, 1u);
        if (ticket == gridDim.x - 1u) {
            const double total = atomicAdd(&g_acc, 0.0);
            out[0] = (float)(total * inv_bs);
            g_acc = 0.0;          // reset for next graph replay
            __threadfence();
            g_counter = 0u;
        }
    }
}

extern "C" void kernel_launch(void* const* d_in, const int* in_sizes, int n_in,
                              void* d_out, int out_size) {
    const float* pred = (const float*)d_in[0];
    const float* targ = (const float*)d_in[1];
    const long long n = (long long)in_sizes[0];
    const int total_cells = (int)(n / CH);            // bs * 49
    const int bs = total_cells / (S_GRID * S_GRID);
    const int ntiles = total_cells / TILE;

    int grid = ntiles < MAX_BLOCKS ? ntiles : MAX_BLOCKS;
    if (grid < 1) grid = 1;

    cudaFuncSetAttribute(yolo_loss_kernel,
                         cudaFuncAttributeMaxDynamicSharedMemorySize, SMEM_BYTES);
    yolo_loss_kernel<<<grid, NTHREADS, SMEM_BYTES>>>(pred, targ, total_cells,
                                                     (float*)d_out,
                                                     1.0 / (double)bs);
}

// round 13
// speedup vs baseline: 1.0749x; 1.0047x over previous
#include <cuda_runtime.h>
#include <cstdint>

// YOLO loss: pred/target (bs, 7, 7, 30) f32 -> scalar f32.
// Warp-specialized streaming pipeline: warp 4 (lane 0) is a dedicated
// producer running the whole cp.async.bulk issue loop (empty-wait -> fill),
// warps 0-3 are pure consumers (full-wait -> compute -> empty-arrive).
// 3-stage ring, TILE=128, grid-strided tiles, last-block finalize.

#define S_GRID 7
#define CH 30
#define TILE 128
#define CONSUMERS 128                       // 4 consumer warps
#define NTHREADS 160                        // + 1 producer warp
#define STAGES 3
#define SFLOATS (TILE * CH)                 // 3840 floats per tensor per stage
#define STAGE_FLOATS (2 * SFLOATS)          // 7680 floats (pred + targ)
#define STAGE_BYTES (STAGE_FLOATS * 4)      // 30720 B
#define HALF_BYTES (SFLOATS * 4)            // 15360 B
#define SMEM_BYTES (STAGES * STAGE_BYTES)   // 92160 B -> 2 CTAs/SM
#define MAX_BLOCKS 296                      // 2 * 148

__device__ double g_acc = 0.0;
__device__ unsigned int g_counter = 0u;

__device__ __forceinline__ void mbar_init(uint32_t mbar, uint32_t cnt) {
    asm volatile("mbarrier.init.shared.b64 [%0], %1;" :: "r"(mbar), "r"(cnt) : "memory");
}
__device__ __forceinline__ void mbar_expect_tx(uint32_t mbar, uint32_t bytes) {
    asm volatile("mbarrier.arrive.expect_tx.shared.b64 _, [%0], %1;"
                 :: "r"(mbar), "r"(bytes) : "memory");
}
__device__ __forceinline__ void mbar_arrive(uint32_t mbar) {
    asm volatile("mbarrier.arrive.shared.b64 _, [%0];" :: "r"(mbar) : "memory");
}
__device__ __forceinline__ void mbar_wait(uint32_t mbar, uint32_t parity) {
    asm volatile(
        "{\n\t"
        ".reg .pred P;\n\t"
        "WAIT_%=:\n\t"
        "mbarrier.try_wait.parity.acquire.cta.shared::cta.b64 P, [%0], %1, 0x989680;\n\t"
        "@P bra.uni DONE_%=;\n\t"
        "bra.uni WAIT_%=;\n\t"
        "DONE_%=:\n\t"
        "}" :: "r"(mbar), "r"(parity) : "memory");
}
__device__ __forceinline__ void bulk_g2s(uint32_t dst, const void* src,
                                         uint32_t bytes, uint32_t mbar) {
    asm volatile(
        "cp.async.bulk.shared::cta.global.mbarrier::complete_tx::bytes [%0], [%1], %2, [%3];"
        :: "r"(dst), "l"(src), "r"(bytes), "r"(mbar) : "memory");
}

// Per-cell loss; p/t point at 30 contiguous floats (smem or gmem).
__device__ __forceinline__ float cell_loss(const float* __restrict__ p,
                                           const float* __restrict__ t)
{
    const float obj = (t[4] > 0.0f) ? 1.0f : 0.0f;

    const float dn0 = p[4] - t[4];
    const float dn1 = p[9] - t[9];
    const float noobj = dn0 * dn0 + dn1 * dn1;

    float cls = 0.0f;
    #pragma unroll
    for (int k = 10; k < 30; k++) {
        const float d = p[k] - t[k];
        cls = fmaf(d, d, cls);
    }

    const float invS = 1.0f / (float)S_GRID;
    const float tx = t[0] * invS, ty = t[1] * invS;
    const float tw = t[2], th = t[3];
    const float tx0 = tx - 0.5f * tw, tx1 = tx + 0.5f * tw;
    const float ty0 = ty - 0.5f * th, ty1 = ty + 0.5f * th;
    const float area_t = tw * th;

    float iou0 = 0.0f, iou1 = 0.0f;
    #pragma unroll
    for (int b = 0; b < 2; b++) {
        const float* q = p + 5 * b;
        const float px = q[0] * invS, py = q[1] * invS;
        const float pw = q[2], ph = q[3];
        const float lx = fmaxf(px - 0.5f * pw, tx0);
        const float rx = fminf(px + 0.5f * pw, tx1);
        const float ly = fmaxf(py - 0.5f * ph, ty0);
        const float ry = fminf(py + 0.5f * ph, ty1);
        const float wx = fmaxf(rx - lx, 0.0f);
        const float wy = fmaxf(ry - ly, 0.0f);
        const float inter = wx * wy;
        const float uni = fmaxf(pw * ph + area_t - inter, 1e-10f);
        const float iou = inter / uni;
        if (b == 0) iou0 = iou; else iou1 = iou;
    }
    // jnp.argmax picks first max -> box 1 only on strict greater.
    const int rb = (iou1 > iou0) ? 1 : 0;
    const float miou = fmaxf(iou0, iou1);

    const float* q  = p + 5 * rb;
    const float* tq = t + 5 * rb;
    const float dx = q[0] - tq[0];
    const float dy = q[1] - tq[1];
    const float lxy = dx * dx + dy * dy;
    const float dw = sqrtf(q[2]) - sqrtf(tq[2]);
    const float dh = sqrtf(q[3]) - sqrtf(tq[3]);
    const float lwh = dw * dw + dh * dh;
    const float dob = q[4] - miou;
    const float lobj = dob * dob;

    return obj * (5.0f * (lxy + lwh) + lobj + cls)
         + 0.5f * (1.0f - obj) * noobj;
}

__global__ __launch_bounds__(NTHREADS) void yolo_loss_kernel(
    const float* __restrict__ pred,
    const float* __restrict__ targ,
    int total_cells,
    float* __restrict__ out,
    double inv_bs)
{
    extern __shared__ float smem[];
    __shared__ __align__(8) uint64_t full_mbar[STAGES];
    __shared__ __align__(8) uint64_t empty_mbar[STAGES];
    __shared__ float warp_sums[CONSUMERS / 32];

    const int tid = threadIdx.x;
    const int lane = tid & 31;
    const uint32_t smem_u32 = (uint32_t)__cvta_generic_to_shared(smem);
    const uint32_t full0  = (uint32_t)__cvta_generic_to_shared(full_mbar);
    const uint32_t empty0 = (uint32_t)__cvta_generic_to_shared(empty_mbar);
    const char* predc = (const char*)pred;
    const char* targc = (const char*)targ;

    const int ntiles = total_cells / TILE;
    const int rem = total_cells - ntiles * TILE;
    const long long stride = gridDim.x;
    const long long t0 = blockIdx.x;

    if (tid == 0) {
        #pragma unroll
        for (int s = 0; s < STAGES; s++) {
            mbar_init(full0  + 8u * s, 1u);             // producer expect_tx
            mbar_init(empty0 + 8u * s, CONSUMERS / 32); // one arrive per consumer warp
        }
    }
    __syncthreads();

    float loss = 0.0f;

    if (tid >= CONSUMERS) {
        // ── Producer warp (warp 4). Lane 0 runs the whole issue loop, racing
        // up to STAGES tiles ahead of the consumers.
        if (lane == 0) {
            long long k = 0;
            for (long long t = t0; t < ntiles; t += stride, k++) {
                const int s = (int)(k % STAGES);
                const long long c = k / STAGES;   // fill count for this stage
                if (c > 0) {
                    // Wait for consumers to drain the previous tile in s.
                    mbar_wait(empty0 + 8u * s, (uint32_t)((c - 1) & 1));
                }
                const uint32_t dst = smem_u32 + (uint32_t)s * STAGE_BYTES;
                mbar_expect_tx(full0 + 8u * s, STAGE_BYTES);
                bulk_g2s(dst,              predc + t * (long long)HALF_BYTES,
                         HALF_BYTES, full0 + 8u * s);
                bulk_g2s(dst + HALF_BYTES, targc + t * (long long)HALF_BYTES,
                         HALF_BYTES, full0 + 8u * s);
            }
        }
    } else {
        // ── Consumer warps (0-3).
        long long k = 0;
        for (long long t = t0; t < ntiles; t += stride, k++) {
            const int s = (int)(k % STAGES);
            const long long c = k / STAGES;

            mbar_wait(full0 + 8u * s, (uint32_t)(c & 1));

            const float* p  = smem + s * STAGE_FLOATS + tid * CH;
            const float* tt = smem + s * STAGE_FLOATS + SFLOATS + tid * CH;
            loss += cell_loss(p, tt);

            __syncwarp();
            if (lane == 0) mbar_arrive(empty0 + 8u * s);
        }

        // Tail cells (total_cells % TILE; zero at bench shape), block 0.
        if (rem && blockIdx.x == 0 && tid < rem) {
            const long long cc = (long long)ntiles * TILE + tid;
            loss += cell_loss(pred + cc * CH, targ + cc * CH);
        }
    }

    // Reduction: consumer warps reduce; producer warp contributes nothing.
    #pragma unroll
    for (int o = 16; o > 0; o >>= 1)
        loss += __shfl_xor_sync(0xffffffffu, loss, o);
    if (tid < CONSUMERS && lane == 0) warp_sums[tid >> 5] = loss;
    __syncthreads();

    if (tid == 0) {
        const float bsum = warp_sums[0] + warp_sums[1] + warp_sums[2] + warp_sums[3];
        atomicAdd(&g_acc, (double)bsum);
        __threadfence();
        const unsigned int ticket = atomicAdd(&g_counter, 1u);
        if (ticket == gridDim.x - 1u) {
            const double total = atomicAdd(&g_acc, 0.0);
            out[0] = (float)(total * inv_bs);
            g_acc = 0.0;          // reset for next graph replay
            __threadfence();
            g_counter = 0u;
        }
    }
}

extern "C" void kernel_launch(void* const* d_in, const int* in_sizes, int n_in,
                              void* d_out, int out_size) {
    const float* pred = (const float*)d_in[0];
    const float* targ = (const float*)d_in[1];
    const long long n = (long long)in_sizes[0];
    const int total_cells = (int)(n / CH);            // bs * 49
    const int bs = total_cells / (S_GRID * S_GRID);
    const int ntiles = total_cells / TILE;

    int grid = ntiles < MAX_BLOCKS ? ntiles : MAX_BLOCKS;
    if (grid < 1) grid = 1;

    cudaFuncSetAttribute(yolo_loss_kernel,
                         cudaFuncAttributeMaxDynamicSharedMemorySize, SMEM_BYTES);
    yolo_loss_kernel<<<grid, NTHREADS, SMEM_BYTES>>>(pred, targ, total_cells,
                                                     (float*)d_out,
                                                     1.0 / (double)bs);
}